// round 3
// baseline (speedup 1.0000x reference)
#include <cuda_runtime.h>

// ---------------- problem constants ----------------
#define NNODES 50000
#define NEDGES 800000
#define DH     128
#define DOUT   64

// ---------------- device scratch (no allocs allowed) ----------------
__device__ int   g_is32;                      // 1 if edge_index is int32-packed
__device__ int   g_src[NEDGES];
__device__ int   g_dst[NEDGES];
__device__ float g_dinv[NNODES];              // deg, then 1/max(deg,1)
__device__ float g_Wt0[128 * 256];            // [k][o] transposed, o<128 -> Wl, else Wr
__device__ float g_Wt1[128 * 256];
__device__ float g_Wt2[128 * 128];            // layer2: 64+64 cols
__device__ float g_z[NNODES * DH];            // h @ Wl^T   (scattered over edges)
__device__ float g_y[NNODES * DH];            // h @ Wr^T   (self path)
__device__ float g_agg[NNODES * DH];
__device__ float g_h[NNODES * DH];            // layer activations

// ---------------- dtype detect ----------------
// Reading the first NEDGES entries as int64 is safe in both layouts
// (NEDGES*8 bytes == 2*NEDGES*4 bytes). If the data is int32-packed, an
// int64 view glues two random indices -> value >= 2^32 almost surely.
__global__ void k_detect(const long long* __restrict__ ei64) {
    int t = threadIdx.x + blockIdx.x * blockDim.x;   // 4096 samples
    long long stride = NEDGES / 4096;
    long long v = ei64[(long long)t * stride];
    if (v < 0 || v >= NNODES) atomicOr(&g_is32, 1);
}

// ---------------- prep kernels ----------------
__global__ void k_prep_edges(const void* __restrict__ ei_raw, float* __restrict__ deg) {
    int i = blockIdx.x * blockDim.x + threadIdx.x;
    if (i >= NEDGES) return;
    int d, s;
    if (g_is32) {
        const int* e = (const int*)ei_raw;
        d = e[i];             // row 0 = dst
        s = e[NEDGES + i];    // row 1 = src
    } else {
        const long long* e = (const long long*)ei_raw;
        d = (int)e[i];
        s = (int)e[NEDGES + i];
    }
    g_dst[i] = d;
    g_src[i] = s;
    atomicAdd(&deg[d], 1.0f);
}

__global__ void k_inv_deg() {
    int i = blockIdx.x * blockDim.x + threadIdx.x;
    if (i >= NNODES) return;
    g_dinv[i] = 1.0f / fmaxf(g_dinv[i], 1.0f);
}

// Wt[k*NC + o] = (o<half ? Wl[o][k] : Wr[o-half][k]);  K is always 128.
__global__ void k_transpose_w(const float* __restrict__ Wl, const float* __restrict__ Wr,
                              float* __restrict__ Wt, int half) {
    int NC = 2 * half;
    int idx = blockIdx.x * blockDim.x + threadIdx.x;
    if (idx >= 128 * NC) return;
    int k = idx / NC;
    int o = idx % NC;
    Wt[idx] = (o < half) ? Wl[o * 128 + k] : Wr[(o - half) * 128 + k];
}

// ---------------- dual GEMM: Z = H @ Wl^T, Y = H @ Wr^T ----------------
// NC = total output cols (2*D). Tile: 64 rows x NC cols per CTA, 256 threads.
template <int NC>
__global__ __launch_bounds__(256, 1)
void k_gemm_dual(const float* __restrict__ H, const float* __restrict__ Wt,
                 float* __restrict__ Z, float* __restrict__ Y) {
    constexpr int D       = NC / 2;
    constexpr int RPT     = NC / 64;       // rows per thread
    constexpr int CGROUPS = NC / 16;       // col groups of 16
    constexpr int HP      = 132;           // padded H row stride

    extern __shared__ float smem[];
    float* sH = smem;                      // 64 x HP
    float* sW = smem + 64 * HP;            // 128 x NC

    const int tid  = threadIdx.x;
    const int row0 = blockIdx.x * 64;

    {
        const float4* s4 = (const float4*)Wt;
        float4*       d4 = (float4*)sW;
        #pragma unroll
        for (int i = tid; i < 128 * NC / 4; i += 256) d4[i] = s4[i];
    }
    {
        const float4* h4 = (const float4*)H;
        #pragma unroll
        for (int i = tid; i < 64 * 32; i += 256) {
            int r = i >> 5, c = i & 31;
            int gr = row0 + r;
            float4 v = (gr < NNODES) ? h4[gr * 32 + c] : make_float4(0.f, 0.f, 0.f, 0.f);
            *(float4*)&sH[r * HP + c * 4] = v;
        }
    }
    __syncthreads();

    const int cg = tid % CGROUPS;
    const int rg = tid / CGROUPS;

    float acc[RPT][16];
    #pragma unroll
    for (int i = 0; i < RPT; ++i)
        #pragma unroll
        for (int j = 0; j < 16; ++j) acc[i][j] = 0.f;

    #pragma unroll 2
    for (int k = 0; k < 128; ++k) {
        float a[RPT];
        #pragma unroll
        for (int i = 0; i < RPT; ++i) a[i] = sH[(rg * RPT + i) * HP + k];
        float4 b[4];
        const float4* bw = (const float4*)&sW[k * NC + cg * 16];
        #pragma unroll
        for (int q = 0; q < 4; ++q) b[q] = bw[q];
        #pragma unroll
        for (int i = 0; i < RPT; ++i) {
            float av = a[i];
            #pragma unroll
            for (int q = 0; q < 4; ++q) {
                acc[i][q * 4 + 0] += av * b[q].x;
                acc[i][q * 4 + 1] += av * b[q].y;
                acc[i][q * 4 + 2] += av * b[q].z;
                acc[i][q * 4 + 3] += av * b[q].w;
            }
        }
    }

    const int  c0    = cg * 16;
    const bool yhalf = (c0 >= D);
    const int  oc    = yhalf ? (c0 - D) : c0;
    float* out = yhalf ? Y : Z;
    #pragma unroll
    for (int i = 0; i < RPT; ++i) {
        int r = row0 + rg * RPT + i;
        if (r < NNODES) {
            #pragma unroll
            for (int q = 0; q < 4; ++q) {
                float4 v = make_float4(acc[i][q * 4 + 0], acc[i][q * 4 + 1],
                                       acc[i][q * 4 + 2], acc[i][q * 4 + 3]);
                *(float4*)&out[r * D + oc + q * 4] = v;
            }
        }
    }
}

// ---------------- edge scatter: agg[dst] += z[src] ----------------
template <int D>
__global__ void k_scatter(const float* __restrict__ Zb, float* __restrict__ Agg) {
    constexpr int CPE = D / 4;
    int t = blockIdx.x * blockDim.x + threadIdx.x;
    int e = t / CPE;
    int c = t % CPE;
    if (e >= NEDGES) return;
    int s = g_src[e];
    int d = g_dst[e];
    const float4 v = *(const float4*)&Zb[s * D + c * 4];
    float* p = &Agg[d * D + c * 4];
    atomicAdd(p + 0, v.x);
    atomicAdd(p + 1, v.y);
    atomicAdd(p + 2, v.z);
    atomicAdd(p + 3, v.w);
}

// ---------------- combine: h = relu(agg*inv + y + b) ----------------
template <int D>
__global__ void k_combine_relu(const float* __restrict__ bias, float* __restrict__ Hout) {
    constexpr int C4 = D / 4;
    int idx = blockIdx.x * blockDim.x + threadIdx.x;
    if (idx >= NNODES * C4) return;
    int row = idx / C4;
    int c   = idx % C4;
    float inv = g_dinv[row];
    float4 a  = *(const float4*)&g_agg[idx * 4];
    float4 yv = *(const float4*)&g_y[idx * 4];
    float4 b  = *(const float4*)&bias[c * 4];
    float4 o;
    o.x = fmaxf(a.x * inv + yv.x + b.x, 0.f);
    o.y = fmaxf(a.y * inv + yv.y + b.y, 0.f);
    o.z = fmaxf(a.z * inv + yv.z + b.z, 0.f);
    o.w = fmaxf(a.w * inv + yv.w + b.w, 0.f);
    *(float4*)&Hout[idx * 4] = o;
}

// ---------------- final layer combine + log_softmax (warp per row, D=64) ----
__global__ void k_final(const float* __restrict__ bias, float* __restrict__ out) {
    int gt   = blockIdx.x * blockDim.x + threadIdx.x;
    int row  = gt >> 5;
    int lane = threadIdx.x & 31;
    if (row >= NNODES) return;
    float inv = g_dinv[row];
    float v0 = g_agg[row * 64 + lane]      * inv + g_y[row * 64 + lane]      + bias[lane];
    float v1 = g_agg[row * 64 + 32 + lane] * inv + g_y[row * 64 + 32 + lane] + bias[32 + lane];
    float m = fmaxf(v0, v1);
    #pragma unroll
    for (int o = 16; o; o >>= 1) m = fmaxf(m, __shfl_xor_sync(0xffffffffu, m, o));
    float s = expf(v0 - m) + expf(v1 - m);
    #pragma unroll
    for (int o = 16; o; o >>= 1) s += __shfl_xor_sync(0xffffffffu, s, o);
    float lse = m + logf(s);
    out[row * 64 + lane]      = v0 - lse;
    out[row * 64 + 32 + lane] = v1 - lse;
}

// ---------------- host launch ----------------
extern "C" void kernel_launch(void* const* d_in, const int* in_sizes, int n_in,
                              void* d_out, int out_size) {
    const float* x   = (const float*)d_in[0];
    const void*  ei  = d_in[1];                       // int32 or int64, detected on device
    const float* Wl0 = (const float*)d_in[2];
    const float* bl0 = (const float*)d_in[3];
    const float* Wr0 = (const float*)d_in[4];
    const float* Wl1 = (const float*)d_in[5];
    const float* bl1 = (const float*)d_in[6];
    const float* Wr1 = (const float*)d_in[7];
    const float* Wl2 = (const float*)d_in[8];
    const float* bl2 = (const float*)d_in[9];
    const float* Wr2 = (const float*)d_in[10];
    float* out = (float*)d_out;
    (void)in_sizes; (void)n_in; (void)out_size;

    void *p_is32, *p_dinv, *p_Wt0, *p_Wt1, *p_Wt2, *p_z, *p_y, *p_agg, *p_h;
    cudaGetSymbolAddress(&p_is32, g_is32);
    cudaGetSymbolAddress(&p_dinv, g_dinv);
    cudaGetSymbolAddress(&p_Wt0, g_Wt0);
    cudaGetSymbolAddress(&p_Wt1, g_Wt1);
    cudaGetSymbolAddress(&p_Wt2, g_Wt2);
    cudaGetSymbolAddress(&p_z,   g_z);
    cudaGetSymbolAddress(&p_y,   g_y);
    cudaGetSymbolAddress(&p_agg, g_agg);
    cudaGetSymbolAddress(&p_h,   g_h);

    const int SMEM256 = (64 * 132 + 128 * 256) * 4;  // 164864
    const int SMEM128 = (64 * 132 + 128 * 128) * 4;  //  99328
    cudaFuncSetAttribute(k_gemm_dual<256>, cudaFuncAttributeMaxDynamicSharedMemorySize, SMEM256);
    cudaFuncSetAttribute(k_gemm_dual<128>, cudaFuncAttributeMaxDynamicSharedMemorySize, SMEM128);

    const int GB = (NNODES + 63) / 64;  // 782 row-tiles

    // ---- prep (per-launch, deterministic) ----
    cudaMemsetAsync(p_is32, 0, sizeof(int));
    cudaMemsetAsync(p_dinv, 0, NNODES * sizeof(float));
    k_detect<<<16, 256>>>((const long long*)ei);
    k_prep_edges<<<(NEDGES + 255) / 256, 256>>>(ei, (float*)p_dinv);
    k_inv_deg<<<(NNODES + 255) / 256, 256>>>();
    k_transpose_w<<<(128 * 256 + 255) / 256, 256>>>(Wl0, Wr0, (float*)p_Wt0, 128);
    k_transpose_w<<<(128 * 256 + 255) / 256, 256>>>(Wl1, Wr1, (float*)p_Wt1, 128);
    k_transpose_w<<<(128 * 128 + 255) / 256, 256>>>(Wl2, Wr2, (float*)p_Wt2, 64);

    // ---- layer 0 (in: x, D=128) ----
    cudaMemsetAsync(p_agg, 0, (size_t)NNODES * 128 * sizeof(float));
    k_gemm_dual<256><<<GB, 256, SMEM256>>>(x, (const float*)p_Wt0, (float*)p_z, (float*)p_y);
    k_scatter<128><<<(NEDGES * 32 + 255) / 256, 256>>>((const float*)p_z, (float*)p_agg);
    k_combine_relu<128><<<(NNODES * 32 + 255) / 256, 256>>>(bl0, (float*)p_h);

    // ---- layer 1 (in: h, D=128) ----
    cudaMemsetAsync(p_agg, 0, (size_t)NNODES * 128 * sizeof(float));
    k_gemm_dual<256><<<GB, 256, SMEM256>>>((const float*)p_h, (const float*)p_Wt1,
                                           (float*)p_z, (float*)p_y);
    k_scatter<128><<<(NEDGES * 32 + 255) / 256, 256>>>((const float*)p_z, (float*)p_agg);
    k_combine_relu<128><<<(NNODES * 32 + 255) / 256, 256>>>(bl1, (float*)p_h);

    // ---- layer 2 (in: h, D=64) + log_softmax ----
    cudaMemsetAsync(p_agg, 0, (size_t)NNODES * 64 * sizeof(float));
    k_gemm_dual<128><<<GB, 256, SMEM128>>>((const float*)p_h, (const float*)p_Wt2,
                                           (float*)p_z, (float*)p_y);
    k_scatter<64><<<(NEDGES * 16 + 255) / 256, 256>>>((const float*)p_z, (float*)p_agg);
    k_final<<<(NNODES * 32 + 255) / 256, 256>>>(bl2, out);
}

// round 4
// speedup vs baseline: 1.5956x; 1.5956x over previous
#include <cuda_runtime.h>

// ---------------- problem constants ----------------
#define NNODES 50000
#define NEDGES 800000
#define DH     128
#define SCAN_B 256
#define NBLK   ((NNODES + SCAN_B - 1) / SCAN_B)   // 196

// ---------------- device scratch (no allocs allowed) ----------------
__device__ int   g_is32;                      // 1 if edge_index is int32-packed
__device__ int   g_src[NEDGES];
__device__ int   g_dst[NEDGES];
__device__ int   g_deg[NNODES];
__device__ int   g_rowptr[NNODES + 1];
__device__ int   g_fill[NNODES];
__device__ int   g_csrc[NEDGES];              // CSR: src ids grouped by dst
__device__ int   g_bsum[NBLK];
__device__ int   g_boff[NBLK];
__device__ float g_dinv[NNODES];
__device__ float g_Wt0[128 * 256];            // [k][o], o<128 -> Wl, else Wr
__device__ float g_Wt1[128 * 256];
__device__ float g_Wt2[128 * 128];            // layer2: 64+64 cols
__device__ float g_z[NNODES * DH];            // h @ Wl^T (gathered over edges)
__device__ float g_y[NNODES * DH];            // h @ Wr^T (self path)
__device__ float g_h[NNODES * DH];            // layer activations

// ---------------- dtype detect (int64 view safe in both layouts) --------
__global__ void k_detect(const long long* __restrict__ ei64) {
    int t = threadIdx.x + blockIdx.x * blockDim.x;   // 4096 samples
    long long stride = NEDGES / 4096;
    long long v = ei64[(long long)t * stride];
    if (v < 0 || v >= NNODES) atomicOr(&g_is32, 1);
}

// ---------------- edge decode + integer degree ----------------
__global__ void k_prep_edges(const void* __restrict__ ei_raw) {
    int i = blockIdx.x * blockDim.x + threadIdx.x;
    if (i >= NEDGES) return;
    int d, s;
    if (g_is32) {
        const int* e = (const int*)ei_raw;
        d = e[i];             // row 0 = dst
        s = e[NEDGES + i];    // row 1 = src
    } else {
        const long long* e = (const long long*)ei_raw;
        d = (int)e[i];
        s = (int)e[NEDGES + i];
    }
    g_dst[i] = d;
    g_src[i] = s;
    atomicAdd(&g_deg[d], 1);
}

// ---------------- CSR build: block scan over degrees ----------------
__global__ void k_scan1() {
    __shared__ int s[SCAN_B];
    int tid = threadIdx.x;
    int i = blockIdx.x * SCAN_B + tid;
    int v = (i < NNODES) ? g_deg[i] : 0;
    s[tid] = v;
    __syncthreads();
    #pragma unroll
    for (int off = 1; off < SCAN_B; off <<= 1) {
        int t = (tid >= off) ? s[tid - off] : 0;
        __syncthreads();
        s[tid] += t;
        __syncthreads();
    }
    if (i < NNODES) g_rowptr[i + 1] = s[tid];          // inclusive, block-local
    if (tid == SCAN_B - 1) g_bsum[blockIdx.x] = s[tid];
}

__global__ void k_scan2() {   // single block, exclusive scan of block sums
    __shared__ int s[SCAN_B];
    int tid = threadIdx.x;
    int v = (tid < NBLK) ? g_bsum[tid] : 0;
    s[tid] = v;
    __syncthreads();
    #pragma unroll
    for (int off = 1; off < SCAN_B; off <<= 1) {
        int t = (tid >= off) ? s[tid - off] : 0;
        __syncthreads();
        s[tid] += t;
        __syncthreads();
    }
    if (tid < NBLK) g_boff[tid] = s[tid] - v;          // exclusive
}

__global__ void k_scan3() {
    int i = blockIdx.x * blockDim.x + threadIdx.x;
    if (i == 0) g_rowptr[0] = 0;
    if (i < NNODES) {
        g_rowptr[i + 1] += g_boff[i / SCAN_B];
        g_dinv[i] = 1.0f / fmaxf((float)g_deg[i], 1.0f);
    }
}

__global__ void k_fill() {
    int i = blockIdx.x * blockDim.x + threadIdx.x;
    if (i >= NEDGES) return;
    int d = g_dst[i];
    int pos = g_rowptr[d] + atomicAdd(&g_fill[d], 1);
    g_csrc[pos] = g_src[i];
}

// ---------------- weight transpose: Wt[k*NC+o] ----------------
__global__ void k_transpose_w(const float* __restrict__ Wl, const float* __restrict__ Wr,
                              float* __restrict__ Wt, int half) {
    int NC = 2 * half;
    int idx = blockIdx.x * blockDim.x + threadIdx.x;
    if (idx >= 128 * NC) return;
    int k = idx / NC;
    int o = idx % NC;
    Wt[idx] = (o < half) ? Wl[o * 128 + k] : Wr[(o - half) * 128 + k];
}

// ---------------- dual GEMM: Z = H @ Wl^T, Y = H @ Wr^T ----------------
template <int NC>
__global__ __launch_bounds__(256, 1)
void k_gemm_dual(const float* __restrict__ H, const float* __restrict__ Wt,
                 float* __restrict__ Z, float* __restrict__ Y) {
    constexpr int D       = NC / 2;
    constexpr int RPT     = NC / 64;
    constexpr int CGROUPS = NC / 16;
    constexpr int HP      = 132;

    extern __shared__ float smem[];
    float* sH = smem;                      // 64 x HP
    float* sW = smem + 64 * HP;            // 128 x NC

    const int tid  = threadIdx.x;
    const int row0 = blockIdx.x * 64;

    {
        const float4* s4 = (const float4*)Wt;
        float4*       d4 = (float4*)sW;
        #pragma unroll
        for (int i = tid; i < 128 * NC / 4; i += 256) d4[i] = s4[i];
    }
    {
        const float4* h4 = (const float4*)H;
        #pragma unroll
        for (int i = tid; i < 64 * 32; i += 256) {
            int r = i >> 5, c = i & 31;
            int gr = row0 + r;
            float4 v = (gr < NNODES) ? h4[gr * 32 + c] : make_float4(0.f, 0.f, 0.f, 0.f);
            *(float4*)&sH[r * HP + c * 4] = v;
        }
    }
    __syncthreads();

    const int cg = tid % CGROUPS;
    const int rg = tid / CGROUPS;

    float acc[RPT][16];
    #pragma unroll
    for (int i = 0; i < RPT; ++i)
        #pragma unroll
        for (int j = 0; j < 16; ++j) acc[i][j] = 0.f;

    #pragma unroll 2
    for (int k = 0; k < 128; ++k) {
        float a[RPT];
        #pragma unroll
        for (int i = 0; i < RPT; ++i) a[i] = sH[(rg * RPT + i) * HP + k];
        float4 b[4];
        const float4* bw = (const float4*)&sW[k * NC + cg * 16];
        #pragma unroll
        for (int q = 0; q < 4; ++q) b[q] = bw[q];
        #pragma unroll
        for (int i = 0; i < RPT; ++i) {
            float av = a[i];
            #pragma unroll
            for (int q = 0; q < 4; ++q) {
                acc[i][q * 4 + 0] += av * b[q].x;
                acc[i][q * 4 + 1] += av * b[q].y;
                acc[i][q * 4 + 2] += av * b[q].z;
                acc[i][q * 4 + 3] += av * b[q].w;
            }
        }
    }

    const int  c0    = cg * 16;
    const bool yhalf = (c0 >= D);
    const int  oc    = yhalf ? (c0 - D) : c0;
    float* out = yhalf ? Y : Z;
    #pragma unroll
    for (int i = 0; i < RPT; ++i) {
        int r = row0 + rg * RPT + i;
        if (r < NNODES) {
            #pragma unroll
            for (int q = 0; q < 4; ++q) {
                float4 v = make_float4(acc[i][q * 4 + 0], acc[i][q * 4 + 1],
                                       acc[i][q * 4 + 2], acc[i][q * 4 + 3]);
                *(float4*)&out[r * D + oc + q * 4] = v;
            }
        }
    }
}

// -------- fused gather + combine + relu (D=128): warp per dst node --------
__global__ __launch_bounds__(256)
void k_gather_combine128(const float* __restrict__ Z, const float* __restrict__ Yb,
                         const float* __restrict__ bias, float* __restrict__ Hout) {
    int w    = (blockIdx.x * blockDim.x + threadIdx.x) >> 5;
    int lane = threadIdx.x & 31;
    if (w >= NNODES) return;
    int j  = g_rowptr[w];
    int e  = g_rowptr[w + 1];
    const float4* z4 = (const float4*)Z;
    float4 a0 = make_float4(0.f, 0.f, 0.f, 0.f);
    float4 a1 = make_float4(0.f, 0.f, 0.f, 0.f);
    for (; j + 1 < e; j += 2) {
        int s0 = g_csrc[j], s1 = g_csrc[j + 1];
        float4 v0 = z4[s0 * 32 + lane];
        float4 v1 = z4[s1 * 32 + lane];
        a0.x += v0.x; a0.y += v0.y; a0.z += v0.z; a0.w += v0.w;
        a1.x += v1.x; a1.y += v1.y; a1.z += v1.z; a1.w += v1.w;
    }
    if (j < e) {
        int s0 = g_csrc[j];
        float4 v0 = z4[s0 * 32 + lane];
        a0.x += v0.x; a0.y += v0.y; a0.z += v0.z; a0.w += v0.w;
    }
    float inv = g_dinv[w];
    float4 yv = ((const float4*)Yb)[w * 32 + lane];
    float4 bv = ((const float4*)bias)[lane];
    float4 o;
    o.x = fmaxf((a0.x + a1.x) * inv + yv.x + bv.x, 0.f);
    o.y = fmaxf((a0.y + a1.y) * inv + yv.y + bv.y, 0.f);
    o.z = fmaxf((a0.z + a1.z) * inv + yv.z + bv.z, 0.f);
    o.w = fmaxf((a0.w + a1.w) * inv + yv.w + bv.w, 0.f);
    ((float4*)Hout)[w * 32 + lane] = o;
}

// -------- fused gather + combine + log_softmax (D=64): warp per node -----
__global__ __launch_bounds__(256)
void k_gather_final64(const float* __restrict__ Z, const float* __restrict__ Yb,
                      const float* __restrict__ bias, float* __restrict__ out) {
    int w    = (blockIdx.x * blockDim.x + threadIdx.x) >> 5;
    int lane = threadIdx.x & 31;
    if (w >= NNODES) return;
    int j = g_rowptr[w];
    int e = g_rowptr[w + 1];
    const float2* z2 = (const float2*)Z;
    float2 a0 = make_float2(0.f, 0.f);
    float2 a1 = make_float2(0.f, 0.f);
    for (; j + 1 < e; j += 2) {
        int s0 = g_csrc[j], s1 = g_csrc[j + 1];
        float2 v0 = z2[s0 * 32 + lane];
        float2 v1 = z2[s1 * 32 + lane];
        a0.x += v0.x; a0.y += v0.y;
        a1.x += v1.x; a1.y += v1.y;
    }
    if (j < e) {
        int s0 = g_csrc[j];
        float2 v0 = z2[s0 * 32 + lane];
        a0.x += v0.x; a0.y += v0.y;
    }
    float inv = g_dinv[w];
    float2 yv = ((const float2*)Yb)[w * 32 + lane];
    float2 bv = ((const float2*)bias)[lane];
    float v0 = (a0.x + a1.x) * inv + yv.x + bv.x;
    float v1 = (a0.y + a1.y) * inv + yv.y + bv.y;
    float m = fmaxf(v0, v1);
    #pragma unroll
    for (int o = 16; o; o >>= 1) m = fmaxf(m, __shfl_xor_sync(0xffffffffu, m, o));
    float s = expf(v0 - m) + expf(v1 - m);
    #pragma unroll
    for (int o = 16; o; o >>= 1) s += __shfl_xor_sync(0xffffffffu, s, o);
    float lse = m + logf(s);
    out[w * 64 + lane * 2 + 0] = v0 - lse;
    out[w * 64 + lane * 2 + 1] = v1 - lse;
}

// ---------------- host launch ----------------
extern "C" void kernel_launch(void* const* d_in, const int* in_sizes, int n_in,
                              void* d_out, int out_size) {
    const float* x   = (const float*)d_in[0];
    const void*  ei  = d_in[1];                       // int32 or int64, device-detected
    const float* Wl0 = (const float*)d_in[2];
    const float* bl0 = (const float*)d_in[3];
    const float* Wr0 = (const float*)d_in[4];
    const float* Wl1 = (const float*)d_in[5];
    const float* bl1 = (const float*)d_in[6];
    const float* Wr1 = (const float*)d_in[7];
    const float* Wl2 = (const float*)d_in[8];
    const float* bl2 = (const float*)d_in[9];
    const float* Wr2 = (const float*)d_in[10];
    float* out = (float*)d_out;
    (void)in_sizes; (void)n_in; (void)out_size;

    void *p_is32, *p_deg, *p_fill, *p_Wt0, *p_Wt1, *p_Wt2, *p_z, *p_y, *p_h;
    cudaGetSymbolAddress(&p_is32, g_is32);
    cudaGetSymbolAddress(&p_deg,  g_deg);
    cudaGetSymbolAddress(&p_fill, g_fill);
    cudaGetSymbolAddress(&p_Wt0, g_Wt0);
    cudaGetSymbolAddress(&p_Wt1, g_Wt1);
    cudaGetSymbolAddress(&p_Wt2, g_Wt2);
    cudaGetSymbolAddress(&p_z,   g_z);
    cudaGetSymbolAddress(&p_y,   g_y);
    cudaGetSymbolAddress(&p_h,   g_h);

    const int SMEM256 = (64 * 132 + 128 * 256) * 4;  // 164864
    const int SMEM128 = (64 * 132 + 128 * 128) * 4;  //  99328
    cudaFuncSetAttribute(k_gemm_dual<256>, cudaFuncAttributeMaxDynamicSharedMemorySize, SMEM256);
    cudaFuncSetAttribute(k_gemm_dual<128>, cudaFuncAttributeMaxDynamicSharedMemorySize, SMEM128);

    const int GB = (NNODES + 63) / 64;               // 782 row-tiles
    const int GW = (NNODES * 32 + 255) / 256;        // warp-per-node grids (6250)
    const int GE = (NEDGES + 255) / 256;
    const int GN = (NNODES + 255) / 256;

    // ---- prep: decode edges, build CSR, transpose weights ----
    cudaMemsetAsync(p_is32, 0, sizeof(int));
    cudaMemsetAsync(p_deg,  0, NNODES * sizeof(int));
    cudaMemsetAsync(p_fill, 0, NNODES * sizeof(int));
    k_detect<<<16, 256>>>((const long long*)ei);
    k_prep_edges<<<GE, 256>>>(ei);
    k_scan1<<<NBLK, SCAN_B>>>();
    k_scan2<<<1, SCAN_B>>>();
    k_scan3<<<GN, 256>>>();
    k_fill<<<GE, 256>>>();
    k_transpose_w<<<(128 * 256 + 255) / 256, 256>>>(Wl0, Wr0, (float*)p_Wt0, 128);
    k_transpose_w<<<(128 * 256 + 255) / 256, 256>>>(Wl1, Wr1, (float*)p_Wt1, 128);
    k_transpose_w<<<(128 * 128 + 255) / 256, 256>>>(Wl2, Wr2, (float*)p_Wt2, 64);

    // ---- layer 0 (in: x, D=128) ----
    k_gemm_dual<256><<<GB, 256, SMEM256>>>(x, (const float*)p_Wt0, (float*)p_z, (float*)p_y);
    k_gather_combine128<<<GW, 256>>>((const float*)p_z, (const float*)p_y, bl0, (float*)p_h);

    // ---- layer 1 (in: h, D=128) ----
    k_gemm_dual<256><<<GB, 256, SMEM256>>>((const float*)p_h, (const float*)p_Wt1,
                                           (float*)p_z, (float*)p_y);
    k_gather_combine128<<<GW, 256>>>((const float*)p_z, (const float*)p_y, bl1, (float*)p_h);

    // ---- layer 2 (in: h, D=64) + log_softmax ----
    k_gemm_dual<128><<<GB, 256, SMEM128>>>((const float*)p_h, (const float*)p_Wt2,
                                           (float*)p_z, (float*)p_y);
    k_gather_final64<<<GW, 256>>>((const float*)p_z, (const float*)p_y, bl2, out);
}

// round 6
// speedup vs baseline: 6.0141x; 3.7691x over previous
#include <cuda_runtime.h>
#include <cstdint>

// ---------------- problem constants ----------------
#define NNODES 50000
#define NEDGES 800000
#define SCAN_B 256
#define NBLK   ((NNODES + SCAN_B - 1) / SCAN_B)   // 196

// ---------------- device scratch (no allocs allowed) ----------------
__device__ int   g_is32;
__device__ int   g_src[NEDGES];
__device__ int   g_dst[NEDGES];
__device__ int   g_deg[NNODES];
__device__ int   g_rowptr[NNODES + 1];
__device__ int   g_fill[NNODES];
__device__ int   g_csrc[NEDGES];
__device__ int   g_bsum[NBLK];
__device__ int   g_boff[NBLK];
__device__ float g_dinv[NNODES];
__device__ float g_z[NNODES * 128];
__device__ float g_y[NNODES * 128];
__device__ float g_h[NNODES * 128];

__device__ __forceinline__ float to_tf32(float x) {
    float r;
    asm("cvt.rna.tf32.f32 %0, %1;" : "=f"(r) : "f"(x));
    return r;
}

// ---------------- dtype detect ----------------
__global__ void k_detect(const long long* __restrict__ ei64) {
    int t = threadIdx.x + blockIdx.x * blockDim.x;
    long long stride = NEDGES / 4096;
    long long v = ei64[(long long)t * stride];
    if (v < 0 || v >= NNODES) atomicOr(&g_is32, 1);
}

// ---------------- edge decode + degree ----------------
__global__ void k_prep_edges(const void* __restrict__ ei_raw) {
    int i = blockIdx.x * blockDim.x + threadIdx.x;
    if (i >= NEDGES) return;
    int d, s;
    if (g_is32) {
        const int* e = (const int*)ei_raw;
        d = e[i]; s = e[NEDGES + i];
    } else {
        const long long* e = (const long long*)ei_raw;
        d = (int)e[i]; s = (int)e[NEDGES + i];
    }
    g_dst[i] = d;
    g_src[i] = s;
    atomicAdd(&g_deg[d], 1);
}

// ---------------- CSR build ----------------
__global__ void k_scan1() {
    __shared__ int s[SCAN_B];
    int tid = threadIdx.x;
    int i = blockIdx.x * SCAN_B + tid;
    int v = (i < NNODES) ? g_deg[i] : 0;
    s[tid] = v;
    __syncthreads();
    #pragma unroll
    for (int off = 1; off < SCAN_B; off <<= 1) {
        int t = (tid >= off) ? s[tid - off] : 0;
        __syncthreads();
        s[tid] += t;
        __syncthreads();
    }
    if (i < NNODES) g_rowptr[i + 1] = s[tid];
    if (tid == SCAN_B - 1) g_bsum[blockIdx.x] = s[tid];
}
__global__ void k_scan2() {
    __shared__ int s[SCAN_B];
    int tid = threadIdx.x;
    int v = (tid < NBLK) ? g_bsum[tid] : 0;
    s[tid] = v;
    __syncthreads();
    #pragma unroll
    for (int off = 1; off < SCAN_B; off <<= 1) {
        int t = (tid >= off) ? s[tid - off] : 0;
        __syncthreads();
        s[tid] += t;
        __syncthreads();
    }
    if (tid < NBLK) g_boff[tid] = s[tid] - v;
}
__global__ void k_scan3() {
    int i = blockIdx.x * blockDim.x + threadIdx.x;
    if (i == 0) g_rowptr[0] = 0;
    if (i < NNODES) {
        g_rowptr[i + 1] += g_boff[i / SCAN_B];
        g_dinv[i] = 1.0f / fmaxf((float)g_deg[i], 1.0f);
    }
}
__global__ void k_fill() {
    int i = blockIdx.x * blockDim.x + threadIdx.x;
    if (i >= NEDGES) return;
    int d = g_dst[i];
    int pos = g_rowptr[d] + atomicAdd(&g_fill[d], 1);
    g_csrc[pos] = g_src[i];
}

// ---------------- mma.sync tf32 dual GEMM ----------------
// D[128, NC] = A[128,128] @ B[NC,128]^T ; B rows = [Wl ; Wr] as given (K-major
// row-major [n][k] == mma col-major B). 512 threads = 16 warps.
// Warp grid 4x4: warp_m = wid&3 (32-row bands), warp_n = wid>>2 (NC/4-col bands).
template <int NC>
__global__ __launch_bounds__(512, 1)
void k_gemm_mma(const float* __restrict__ H,
                const float* __restrict__ Wl, const float* __restrict__ Wr,
                float* __restrict__ Z, float* __restrict__ Y) {
    constexpr int D   = NC / 2;
    constexpr int NT  = NC / 32;        // n-frags per warp (8 for NC=256, 4 for 128)
    constexpr int ST  = 132;            // padded k-stride (floats)

    extern __shared__ float smem[];
    float* sA = smem;                   // 128 x ST
    float* sB = smem + 128 * ST;        // NC x ST

    const int tid  = threadIdx.x;
    const int wid  = tid >> 5;
    const int lane = tid & 31;
    const int row0 = blockIdx.x * 128;

    // stage A (tf32-rounded)
    {
        const float4* h4 = (const float4*)H;
        #pragma unroll
        for (int i = tid; i < 128 * 32; i += 512) {
            int r = i >> 5, c = i & 31;
            int gr = row0 + r;
            float4 v = make_float4(0.f, 0.f, 0.f, 0.f);
            if (gr < NNODES) v = h4[gr * 32 + c];
            float* p = &sA[r * ST + c * 4];
            p[0] = to_tf32(v.x); p[1] = to_tf32(v.y);
            p[2] = to_tf32(v.z); p[3] = to_tf32(v.w);
        }
    }
    // stage B (tf32-rounded)
    {
        #pragma unroll
        for (int i = tid; i < NC * 32; i += 512) {
            int n = i >> 5, c = i & 31;
            const float4* wsrc = (const float4*)((n < D) ? (Wl + n * 128)
                                                         : (Wr + (n - D) * 128));
            float4 v = wsrc[c];
            float* p = &sB[n * ST + c * 4];
            p[0] = to_tf32(v.x); p[1] = to_tf32(v.y);
            p[2] = to_tf32(v.z); p[3] = to_tf32(v.w);
        }
    }
    __syncthreads();

    const int warp_m = wid & 3;
    const int warp_n = wid >> 2;
    const int lm = lane >> 2;           // groupID (0..7)
    const int lk = lane & 3;            // threadID-in-group (0..3)

    float acc[2][NT][4];
    #pragma unroll
    for (int mi = 0; mi < 2; ++mi)
        #pragma unroll
        for (int ni = 0; ni < NT; ++ni)
            #pragma unroll
            for (int q = 0; q < 4; ++q) acc[mi][ni][q] = 0.f;

    #pragma unroll
    for (int kk = 0; kk < 16; ++kk) {
        const int k0 = kk * 8;
        uint32_t a[2][4];
        #pragma unroll
        for (int mi = 0; mi < 2; ++mi) {
            const int rb = warp_m * 32 + mi * 16;
            a[mi][0] = *(const uint32_t*)&sA[(rb + lm)     * ST + k0 + lk];
            a[mi][1] = *(const uint32_t*)&sA[(rb + 8 + lm) * ST + k0 + lk];
            a[mi][2] = *(const uint32_t*)&sA[(rb + lm)     * ST + k0 + 4 + lk];
            a[mi][3] = *(const uint32_t*)&sA[(rb + 8 + lm) * ST + k0 + 4 + lk];
        }
        uint32_t b[NT][2];
        #pragma unroll
        for (int ni = 0; ni < NT; ++ni) {
            const int nb = warp_n * (NT * 8) + ni * 8;
            b[ni][0] = *(const uint32_t*)&sB[(nb + lm) * ST + k0 + lk];
            b[ni][1] = *(const uint32_t*)&sB[(nb + lm) * ST + k0 + 4 + lk];
        }
        #pragma unroll
        for (int mi = 0; mi < 2; ++mi)
            #pragma unroll
            for (int ni = 0; ni < NT; ++ni) {
                asm volatile(
                    "mma.sync.aligned.m16n8k8.row.col.f32.tf32.tf32.f32 "
                    "{%0,%1,%2,%3}, {%4,%5,%6,%7}, {%8,%9}, {%0,%1,%2,%3};"
                    : "+f"(acc[mi][ni][0]), "+f"(acc[mi][ni][1]),
                      "+f"(acc[mi][ni][2]), "+f"(acc[mi][ni][3])
                    : "r"(a[mi][0]), "r"(a[mi][1]), "r"(a[mi][2]), "r"(a[mi][3]),
                      "r"(b[ni][0]), "r"(b[ni][1]));
            }
    }

    // epilogue: warp_n 0,1 -> Z ; warp_n 2,3 -> Y (whole warp in one half)
    {
        const bool yhalf = (warp_n >= 2);
        float* dst = yhalf ? Y : Z;
        const int cbase = warp_n * (NT * 8) - (yhalf ? D : 0);
        #pragma unroll
        for (int mi = 0; mi < 2; ++mi) {
            const int rl = row0 + warp_m * 32 + mi * 16 + lm;
            const int rh = rl + 8;
            #pragma unroll
            for (int ni = 0; ni < NT; ++ni) {
                const int oc = cbase + ni * 8 + lk * 2;
                if (rl < NNODES)
                    *(float2*)&dst[rl * D + oc] = make_float2(acc[mi][ni][0], acc[mi][ni][1]);
                if (rh < NNODES)
                    *(float2*)&dst[rh * D + oc] = make_float2(acc[mi][ni][2], acc[mi][ni][3]);
            }
        }
    }
}

// -------- fused gather + combine + relu (D=128): warp per dst node --------
__global__ __launch_bounds__(256)
void k_gather_combine128(const float* __restrict__ Z, const float* __restrict__ Yb,
                         const float* __restrict__ bias, float* __restrict__ Hout) {
    int w    = (blockIdx.x * blockDim.x + threadIdx.x) >> 5;
    int lane = threadIdx.x & 31;
    if (w >= NNODES) return;
    int j = g_rowptr[w];
    int e = g_rowptr[w + 1];
    const float4* z4 = (const float4*)Z;
    float4 a0 = make_float4(0.f, 0.f, 0.f, 0.f);
    float4 a1 = make_float4(0.f, 0.f, 0.f, 0.f);
    for (; j + 1 < e; j += 2) {
        int s0 = g_csrc[j], s1 = g_csrc[j + 1];
        float4 v0 = z4[s0 * 32 + lane];
        float4 v1 = z4[s1 * 32 + lane];
        a0.x += v0.x; a0.y += v0.y; a0.z += v0.z; a0.w += v0.w;
        a1.x += v1.x; a1.y += v1.y; a1.z += v1.z; a1.w += v1.w;
    }
    if (j < e) {
        int s0 = g_csrc[j];
        float4 v0 = z4[s0 * 32 + lane];
        a0.x += v0.x; a0.y += v0.y; a0.z += v0.z; a0.w += v0.w;
    }
    float inv = g_dinv[w];
    float4 yv = ((const float4*)Yb)[w * 32 + lane];
    float4 bv = ((const float4*)bias)[lane];
    float4 o;
    o.x = fmaxf((a0.x + a1.x) * inv + yv.x + bv.x, 0.f);
    o.y = fmaxf((a0.y + a1.y) * inv + yv.y + bv.y, 0.f);
    o.z = fmaxf((a0.z + a1.z) * inv + yv.z + bv.z, 0.f);
    o.w = fmaxf((a0.w + a1.w) * inv + yv.w + bv.w, 0.f);
    ((float4*)Hout)[w * 32 + lane] = o;
}

// -------- fused gather + combine + log_softmax (D=64) --------
__global__ __launch_bounds__(256)
void k_gather_final64(const float* __restrict__ Z, const float* __restrict__ Yb,
                      const float* __restrict__ bias, float* __restrict__ out) {
    int w    = (blockIdx.x * blockDim.x + threadIdx.x) >> 5;
    int lane = threadIdx.x & 31;
    if (w >= NNODES) return;
    int j = g_rowptr[w];
    int e = g_rowptr[w + 1];
    const float2* z2 = (const float2*)Z;
    float2 a0 = make_float2(0.f, 0.f);
    float2 a1 = make_float2(0.f, 0.f);
    for (; j + 1 < e; j += 2) {
        int s0 = g_csrc[j], s1 = g_csrc[j + 1];
        float2 v0 = z2[s0 * 32 + lane];
        float2 v1 = z2[s1 * 32 + lane];
        a0.x += v0.x; a0.y += v0.y;
        a1.x += v1.x; a1.y += v1.y;
    }
    if (j < e) {
        int s0 = g_csrc[j];
        float2 v0 = z2[s0 * 32 + lane];
        a0.x += v0.x; a0.y += v0.y;
    }
    float inv = g_dinv[w];
    float2 yv = ((const float2*)Yb)[w * 32 + lane];
    float2 bv = ((const float2*)bias)[lane];
    float v0 = (a0.x + a1.x) * inv + yv.x + bv.x;
    float v1 = (a0.y + a1.y) * inv + yv.y + bv.y;
    float m = fmaxf(v0, v1);
    #pragma unroll
    for (int o = 16; o; o >>= 1) m = fmaxf(m, __shfl_xor_sync(0xffffffffu, m, o));
    float s = expf(v0 - m) + expf(v1 - m);
    #pragma unroll
    for (int o = 16; o; o >>= 1) s += __shfl_xor_sync(0xffffffffu, s, o);
    float lse = m + logf(s);
    out[w * 64 + lane * 2 + 0] = v0 - lse;
    out[w * 64 + lane * 2 + 1] = v1 - lse;
}

// ---------------- host launch ----------------
extern "C" void kernel_launch(void* const* d_in, const int* in_sizes, int n_in,
                              void* d_out, int out_size) {
    const float* x   = (const float*)d_in[0];
    const void*  ei  = d_in[1];
    const float* Wl0 = (const float*)d_in[2];
    const float* bl0 = (const float*)d_in[3];
    const float* Wr0 = (const float*)d_in[4];
    const float* Wl1 = (const float*)d_in[5];
    const float* bl1 = (const float*)d_in[6];
    const float* Wr1 = (const float*)d_in[7];
    const float* Wl2 = (const float*)d_in[8];
    const float* bl2 = (const float*)d_in[9];
    const float* Wr2 = (const float*)d_in[10];
    float* out = (float*)d_out;
    (void)in_sizes; (void)n_in; (void)out_size;

    void *p_is32, *p_deg, *p_fill, *p_z, *p_y, *p_h;
    cudaGetSymbolAddress(&p_is32, g_is32);
    cudaGetSymbolAddress(&p_deg,  g_deg);
    cudaGetSymbolAddress(&p_fill, g_fill);
    cudaGetSymbolAddress(&p_z,    g_z);
    cudaGetSymbolAddress(&p_y,    g_y);
    cudaGetSymbolAddress(&p_h,    g_h);

    const int SM256 = (128 * 132 + 256 * 132) * 4;   // 202752
    const int SM128 = (128 * 132 + 128 * 132) * 4;   // 135168
    cudaFuncSetAttribute(k_gemm_mma<256>, cudaFuncAttributeMaxDynamicSharedMemorySize, SM256);
    cudaFuncSetAttribute(k_gemm_mma<128>, cudaFuncAttributeMaxDynamicSharedMemorySize, SM128);

    const int GT = (NNODES + 127) / 128;          // 391 GEMM tiles
    const int GW = (NNODES * 32 + 255) / 256;     // warp-per-node (6250)
    const int GE = (NEDGES + 255) / 256;
    const int GN = (NNODES + 255) / 256;

    // ---- prep ----
    cudaMemsetAsync(p_is32, 0, sizeof(int));
    cudaMemsetAsync(p_deg,  0, NNODES * sizeof(int));
    cudaMemsetAsync(p_fill, 0, NNODES * sizeof(int));
    k_detect<<<16, 256>>>((const long long*)ei);

    // layer-0 GEMM is edge-independent: overlap with CSR build
    k_gemm_mma<256><<<GT, 512, SM256>>>(x, Wl0, Wr0, (float*)p_z, (float*)p_y);

    k_prep_edges<<<GE, 256>>>(ei);
    k_scan1<<<NBLK, SCAN_B>>>();
    k_scan2<<<1, SCAN_B>>>();
    k_scan3<<<GN, 256>>>();
    k_fill<<<GE, 256>>>();

    // ---- layer 0 combine ----
    k_gather_combine128<<<GW, 256>>>((const float*)p_z, (const float*)p_y, bl0, (float*)p_h);

    // ---- layer 1 ----
    k_gemm_mma<256><<<GT, 512, SM256>>>((const float*)p_h, Wl1, Wr1, (float*)p_z, (float*)p_y);
    k_gather_combine128<<<GW, 256>>>((const float*)p_z, (const float*)p_y, bl1, (float*)p_h);

    // ---- layer 2 + log_softmax ----
    k_gemm_mma<128><<<GT, 512, SM128>>>((const float*)p_h, Wl2, Wr2, (float*)p_z, (float*)p_y);
    k_gather_final64<<<GW, 256>>>((const float*)p_z, (const float*)p_y, bl2, out);
}

// round 7
// speedup vs baseline: 6.4308x; 1.0693x over previous
#include <cuda_runtime.h>
#include <cuda_bf16.h>
#include <cstdint>

// ---------------- problem constants ----------------
#define NNODES 50000
#define NEDGES 800000
#define SCAN_B 256
#define NBLK   ((NNODES + SCAN_B - 1) / SCAN_B)   // 196

// ---------------- device scratch (no allocs allowed) ----------------
__device__ int   g_is32;
__device__ int   g_src[NEDGES];
__device__ int   g_dst[NEDGES];
__device__ int   g_deg[NNODES];
__device__ int   g_rowptr[NNODES + 1];
__device__ int   g_fill[NNODES];
__device__ int   g_csrc[NEDGES];
__device__ int   g_bsum[NBLK];
__device__ float g_dinv[NNODES];
__device__ uint2 g_zb[NNODES * 32];     // z in bf16: 128 cols = 32 uint2 (4 bf16 each)
__device__ float g_y[NNODES * 128];
__device__ float g_h[NNODES * 128];

__device__ __forceinline__ float to_tf32(float x) {
    float r;
    asm("cvt.rna.tf32.f32 %0, %1;" : "=f"(r) : "f"(x));
    return r;
}

// ---------------- dtype detect ----------------
__global__ void k_detect(const long long* __restrict__ ei64) {
    int t = threadIdx.x + blockIdx.x * blockDim.x;
    long long stride = NEDGES / 4096;
    long long v = ei64[(long long)t * stride];
    if (v < 0 || v >= NNODES) atomicOr(&g_is32, 1);
}

// ---------------- edge decode + degree ----------------
__global__ void k_prep_edges(const void* __restrict__ ei_raw) {
    int i = blockIdx.x * blockDim.x + threadIdx.x;
    if (i >= NEDGES) return;
    int d, s;
    if (g_is32) {
        const int* e = (const int*)ei_raw;
        d = e[i]; s = e[NEDGES + i];
    } else {
        const long long* e = (const long long*)ei_raw;
        d = (int)e[i]; s = (int)e[NEDGES + i];
    }
    g_dst[i] = d;
    g_src[i] = s;
    atomicAdd(&g_deg[d], 1);
}

// ---------------- CSR build ----------------
__global__ void k_scan1() {
    __shared__ int s[SCAN_B];
    int tid = threadIdx.x;
    int i = blockIdx.x * SCAN_B + tid;
    int v = (i < NNODES) ? g_deg[i] : 0;
    s[tid] = v;
    __syncthreads();
    #pragma unroll
    for (int off = 1; off < SCAN_B; off <<= 1) {
        int t = (tid >= off) ? s[tid - off] : 0;
        __syncthreads();
        s[tid] += t;
        __syncthreads();
    }
    if (i < NNODES) g_rowptr[i + 1] = s[tid];
    if (tid == SCAN_B - 1) g_bsum[blockIdx.x] = s[tid];
}

// scan3: each block reduces bsum[0..blockIdx) for its offset, then finalizes
__global__ void k_scan3() {
    __shared__ int red[SCAN_B];
    int tid = threadIdx.x;
    int part = (tid < (int)blockIdx.x && tid < NBLK) ? g_bsum[tid] : 0;
    red[tid] = part;
    __syncthreads();
    #pragma unroll
    for (int off = SCAN_B / 2; off > 0; off >>= 1) {
        if (tid < off) red[tid] += red[tid + off];
        __syncthreads();
    }
    int offset = red[0];
    int i = blockIdx.x * SCAN_B + tid;
    if (i == 0) g_rowptr[0] = 0;
    if (i < NNODES) {
        g_rowptr[i + 1] += offset;
        g_dinv[i] = 1.0f / fmaxf((float)g_deg[i], 1.0f);
    }
}
__global__ void k_fill() {
    int i = blockIdx.x * blockDim.x + threadIdx.x;
    if (i >= NEDGES) return;
    int d = g_dst[i];
    int pos = g_rowptr[d] + atomicAdd(&g_fill[d], 1);
    g_csrc[pos] = g_src[i];
}

// ---------------- mma.sync tf32 dual GEMM ----------------
// Z half stored as bf16 (packed pairs), Y half fp32.
template <int NC>
__global__ __launch_bounds__(512, 1)
void k_gemm_mma(const float* __restrict__ H,
                const float* __restrict__ Wl, const float* __restrict__ Wr,
                __nv_bfloat162* __restrict__ Zb, float* __restrict__ Y) {
    constexpr int D   = NC / 2;
    constexpr int NT  = NC / 32;
    constexpr int ST  = 132;

    extern __shared__ float smem[];
    float* sA = smem;                   // 128 x ST
    float* sB = smem + 128 * ST;        // NC x ST

    const int tid  = threadIdx.x;
    const int wid  = tid >> 5;
    const int lane = tid & 31;
    const int row0 = blockIdx.x * 128;

    {
        const float4* h4 = (const float4*)H;
        #pragma unroll
        for (int i = tid; i < 128 * 32; i += 512) {
            int r = i >> 5, c = i & 31;
            int gr = row0 + r;
            float4 v = make_float4(0.f, 0.f, 0.f, 0.f);
            if (gr < NNODES) v = h4[gr * 32 + c];
            float* p = &sA[r * ST + c * 4];
            p[0] = to_tf32(v.x); p[1] = to_tf32(v.y);
            p[2] = to_tf32(v.z); p[3] = to_tf32(v.w);
        }
    }
    {
        #pragma unroll
        for (int i = tid; i < NC * 32; i += 512) {
            int n = i >> 5, c = i & 31;
            const float4* wsrc = (const float4*)((n < D) ? (Wl + n * 128)
                                                         : (Wr + (n - D) * 128));
            float4 v = wsrc[c];
            float* p = &sB[n * ST + c * 4];
            p[0] = to_tf32(v.x); p[1] = to_tf32(v.y);
            p[2] = to_tf32(v.z); p[3] = to_tf32(v.w);
        }
    }
    __syncthreads();

    const int warp_m = wid & 3;
    const int warp_n = wid >> 2;
    const int lm = lane >> 2;
    const int lk = lane & 3;

    float acc[2][NT][4];
    #pragma unroll
    for (int mi = 0; mi < 2; ++mi)
        #pragma unroll
        for (int ni = 0; ni < NT; ++ni)
            #pragma unroll
            for (int q = 0; q < 4; ++q) acc[mi][ni][q] = 0.f;

    #pragma unroll
    for (int kk = 0; kk < 16; ++kk) {
        const int k0 = kk * 8;
        uint32_t a[2][4];
        #pragma unroll
        for (int mi = 0; mi < 2; ++mi) {
            const int rb = warp_m * 32 + mi * 16;
            a[mi][0] = *(const uint32_t*)&sA[(rb + lm)     * ST + k0 + lk];
            a[mi][1] = *(const uint32_t*)&sA[(rb + 8 + lm) * ST + k0 + lk];
            a[mi][2] = *(const uint32_t*)&sA[(rb + lm)     * ST + k0 + 4 + lk];
            a[mi][3] = *(const uint32_t*)&sA[(rb + 8 + lm) * ST + k0 + 4 + lk];
        }
        uint32_t b[NT][2];
        #pragma unroll
        for (int ni = 0; ni < NT; ++ni) {
            const int nb = warp_n * (NT * 8) + ni * 8;
            b[ni][0] = *(const uint32_t*)&sB[(nb + lm) * ST + k0 + lk];
            b[ni][1] = *(const uint32_t*)&sB[(nb + lm) * ST + k0 + 4 + lk];
        }
        #pragma unroll
        for (int mi = 0; mi < 2; ++mi)
            #pragma unroll
            for (int ni = 0; ni < NT; ++ni) {
                asm volatile(
                    "mma.sync.aligned.m16n8k8.row.col.f32.tf32.tf32.f32 "
                    "{%0,%1,%2,%3}, {%4,%5,%6,%7}, {%8,%9}, {%0,%1,%2,%3};"
                    : "+f"(acc[mi][ni][0]), "+f"(acc[mi][ni][1]),
                      "+f"(acc[mi][ni][2]), "+f"(acc[mi][ni][3])
                    : "r"(a[mi][0]), "r"(a[mi][1]), "r"(a[mi][2]), "r"(a[mi][3]),
                      "r"(b[ni][0]), "r"(b[ni][1]));
            }
    }

    // epilogue: warp_n 0,1 -> Z (bf16) ; warp_n 2,3 -> Y (fp32)
    {
        const bool yhalf = (warp_n >= 2);
        const int cbase = warp_n * (NT * 8) - (yhalf ? D : 0);
        #pragma unroll
        for (int mi = 0; mi < 2; ++mi) {
            const int rl = row0 + warp_m * 32 + mi * 16 + lm;
            const int rh = rl + 8;
            #pragma unroll
            for (int ni = 0; ni < NT; ++ni) {
                const int oc = cbase + ni * 8 + lk * 2;
                if (yhalf) {
                    if (rl < NNODES)
                        *(float2*)&Y[rl * D + oc] = make_float2(acc[mi][ni][0], acc[mi][ni][1]);
                    if (rh < NNODES)
                        *(float2*)&Y[rh * D + oc] = make_float2(acc[mi][ni][2], acc[mi][ni][3]);
                } else {
                    if (rl < NNODES)
                        Zb[rl * (D / 2) + oc / 2] =
                            __float22bfloat162_rn(make_float2(acc[mi][ni][0], acc[mi][ni][1]));
                    if (rh < NNODES)
                        Zb[rh * (D / 2) + oc / 2] =
                            __float22bfloat162_rn(make_float2(acc[mi][ni][2], acc[mi][ni][3]));
                }
            }
        }
    }
}

// -------- fused gather + combine + relu (D=128, z bf16): warp per node -----
__global__ __launch_bounds__(256)
void k_gather_combine128(const uint2* __restrict__ Zb, const float* __restrict__ Yb,
                         const float* __restrict__ bias, float* __restrict__ Hout) {
    int w    = (blockIdx.x * blockDim.x + threadIdx.x) >> 5;
    int lane = threadIdx.x & 31;
    if (w >= NNODES) return;
    int j = g_rowptr[w];
    int e = g_rowptr[w + 1];
    float4 a0 = make_float4(0.f, 0.f, 0.f, 0.f);
    float4 a1 = make_float4(0.f, 0.f, 0.f, 0.f);
    for (; j + 1 < e; j += 2) {
        int s0 = g_csrc[j], s1 = g_csrc[j + 1];
        uint2 u0 = Zb[s0 * 32 + lane];
        uint2 u1 = Zb[s1 * 32 + lane];
        float2 f00 = __bfloat1622float2(*(const __nv_bfloat162*)&u0.x);
        float2 f01 = __bfloat1622float2(*(const __nv_bfloat162*)&u0.y);
        float2 f10 = __bfloat1622float2(*(const __nv_bfloat162*)&u1.x);
        float2 f11 = __bfloat1622float2(*(const __nv_bfloat162*)&u1.y);
        a0.x += f00.x; a0.y += f00.y; a0.z += f01.x; a0.w += f01.y;
        a1.x += f10.x; a1.y += f10.y; a1.z += f11.x; a1.w += f11.y;
    }
    if (j < e) {
        int s0 = g_csrc[j];
        uint2 u0 = Zb[s0 * 32 + lane];
        float2 f00 = __bfloat1622float2(*(const __nv_bfloat162*)&u0.x);
        float2 f01 = __bfloat1622float2(*(const __nv_bfloat162*)&u0.y);
        a0.x += f00.x; a0.y += f00.y; a0.z += f01.x; a0.w += f01.y;
    }
    float inv = g_dinv[w];
    float4 yv = ((const float4*)Yb)[w * 32 + lane];
    float4 bv = ((const float4*)bias)[lane];
    float4 o;
    o.x = fmaxf((a0.x + a1.x) * inv + yv.x + bv.x, 0.f);
    o.y = fmaxf((a0.y + a1.y) * inv + yv.y + bv.y, 0.f);
    o.z = fmaxf((a0.z + a1.z) * inv + yv.z + bv.z, 0.f);
    o.w = fmaxf((a0.w + a1.w) * inv + yv.w + bv.w, 0.f);
    ((float4*)Hout)[w * 32 + lane] = o;
}

// -------- fused gather + combine + log_softmax (D=64, z bf16) --------
__global__ __launch_bounds__(256)
void k_gather_final64(const unsigned* __restrict__ Zb, const float* __restrict__ Yb,
                      const float* __restrict__ bias, float* __restrict__ out) {
    int w    = (blockIdx.x * blockDim.x + threadIdx.x) >> 5;
    int lane = threadIdx.x & 31;
    if (w >= NNODES) return;
    int j = g_rowptr[w];
    int e = g_rowptr[w + 1];
    float2 a0 = make_float2(0.f, 0.f);
    float2 a1 = make_float2(0.f, 0.f);
    for (; j + 1 < e; j += 2) {
        int s0 = g_csrc[j], s1 = g_csrc[j + 1];
        unsigned u0 = Zb[s0 * 32 + lane];
        unsigned u1 = Zb[s1 * 32 + lane];
        float2 f0 = __bfloat1622float2(*(const __nv_bfloat162*)&u0);
        float2 f1 = __bfloat1622float2(*(const __nv_bfloat162*)&u1);
        a0.x += f0.x; a0.y += f0.y;
        a1.x += f1.x; a1.y += f1.y;
    }
    if (j < e) {
        int s0 = g_csrc[j];
        unsigned u0 = Zb[s0 * 32 + lane];
        float2 f0 = __bfloat1622float2(*(const __nv_bfloat162*)&u0);
        a0.x += f0.x; a0.y += f0.y;
    }
    float inv = g_dinv[w];
    float2 yv = ((const float2*)Yb)[w * 32 + lane];
    float2 bv = ((const float2*)bias)[lane];
    float v0 = (a0.x + a1.x) * inv + yv.x + bv.x;
    float v1 = (a0.y + a1.y) * inv + yv.y + bv.y;
    float m = fmaxf(v0, v1);
    #pragma unroll
    for (int o = 16; o; o >>= 1) m = fmaxf(m, __shfl_xor_sync(0xffffffffu, m, o));
    float s = expf(v0 - m) + expf(v1 - m);
    #pragma unroll
    for (int o = 16; o; o >>= 1) s += __shfl_xor_sync(0xffffffffu, s, o);
    float lse = m + logf(s);
    out[w * 64 + lane * 2 + 0] = v0 - lse;
    out[w * 64 + lane * 2 + 1] = v1 - lse;
}

// ---------------- host launch ----------------
extern "C" void kernel_launch(void* const* d_in, const int* in_sizes, int n_in,
                              void* d_out, int out_size) {
    const float* x   = (const float*)d_in[0];
    const void*  ei  = d_in[1];
    const float* Wl0 = (const float*)d_in[2];
    const float* bl0 = (const float*)d_in[3];
    const float* Wr0 = (const float*)d_in[4];
    const float* Wl1 = (const float*)d_in[5];
    const float* bl1 = (const float*)d_in[6];
    const float* Wr1 = (const float*)d_in[7];
    const float* Wl2 = (const float*)d_in[8];
    const float* bl2 = (const float*)d_in[9];
    const float* Wr2 = (const float*)d_in[10];
    float* out = (float*)d_out;
    (void)in_sizes; (void)n_in; (void)out_size;

    void *p_is32, *p_deg, *p_fill, *p_zb, *p_y, *p_h;
    cudaGetSymbolAddress(&p_is32, g_is32);
    cudaGetSymbolAddress(&p_deg,  g_deg);
    cudaGetSymbolAddress(&p_fill, g_fill);
    cudaGetSymbolAddress(&p_zb,   g_zb);
    cudaGetSymbolAddress(&p_y,    g_y);
    cudaGetSymbolAddress(&p_h,    g_h);

    const int SM256 = (128 * 132 + 256 * 132) * 4;   // 202752
    const int SM128 = (128 * 132 + 128 * 132) * 4;   // 135168
    cudaFuncSetAttribute(k_gemm_mma<256>, cudaFuncAttributeMaxDynamicSharedMemorySize, SM256);
    cudaFuncSetAttribute(k_gemm_mma<128>, cudaFuncAttributeMaxDynamicSharedMemorySize, SM128);

    const int GT = (NNODES + 127) / 128;
    const int GW = (NNODES * 32 + 255) / 256;
    const int GE = (NEDGES + 255) / 256;
    const int GN = (NNODES + 255) / 256;

    // ---- prep ----
    cudaMemsetAsync(p_is32, 0, sizeof(int));
    cudaMemsetAsync(p_deg,  0, NNODES * sizeof(int));
    cudaMemsetAsync(p_fill, 0, NNODES * sizeof(int));
    k_detect<<<16, 256>>>((const long long*)ei);

    // layer-0 GEMM (edge-independent)
    k_gemm_mma<256><<<GT, 512, SM256>>>(x, Wl0, Wr0, (__nv_bfloat162*)p_zb, (float*)p_y);

    k_prep_edges<<<GE, 256>>>(ei);
    k_scan1<<<NBLK, SCAN_B>>>();
    k_scan3<<<GN, SCAN_B>>>();
    k_fill<<<GE, 256>>>();

    // ---- layer 0 combine ----
    k_gather_combine128<<<GW, 256>>>((const uint2*)p_zb, (const float*)p_y, bl0, (float*)p_h);

    // ---- layer 1 ----
    k_gemm_mma<256><<<GT, 512, SM256>>>((const float*)p_h, Wl1, Wr1,
                                        (__nv_bfloat162*)p_zb, (float*)p_y);
    k_gather_combine128<<<GW, 256>>>((const uint2*)p_zb, (const float*)p_y, bl1, (float*)p_h);

    // ---- layer 2 + log_softmax ----
    k_gemm_mma<128><<<GT, 512, SM128>>>((const float*)p_h, Wl2, Wr2,
                                        (__nv_bfloat162*)p_zb, (float*)p_y);
    k_gather_final64<<<GW, 256>>>((const unsigned*)p_zb, (const float*)p_y, bl2, out);
}